// round 9
// baseline (speedup 1.0000x reference)
#include <cuda_runtime.h>
#include <stdint.h>

// Problem constants (fixed by the dataset)
#define T_  500
#define B_  16
#define S_  256
#define P_  128
#define L_  16

#define SEG   17     // u32 per p-list: [0]=paddedWords | realCnt<<16; 16 words = 64 idx cap
#define STRF  9      // sl4 stride (float4) per s: bank-group (s+tslot)%8 -> conflict-free quarters
#define OST   129    // output-transpose row stride: conflict-free STS
#define PADV (-3.402823466e38f)

// Scratch (__device__ globals; allocation is forbidden). Pure fns of inputs.
__device__ unsigned short g_bitsH[L_ * P_ * 16];   // [lang][p][16] u16 membership halves
__device__ uint32_t      g_list [L_ * P_ * SEG];   // packed u8 index lists, quad-padded

// ---------------------------------------------------------------------------
// Stage 1: membership bitmask. CTA = (lang, 16-s chunk) -> 256 CTAs x 128 thr.
// Thread builds one 16-bit half-word from 16 independent coalesced loads.
// ---------------------------------------------------------------------------
__global__ __launch_bounds__(P_) void build_bits_kernel(const float* __restrict__ mats) {
    const int l  = blockIdx.x >> 4;
    const int hh = blockIdx.x & 15;
    const int p  = threadIdx.x;
    const float* base = mats + ((size_t)l * S_ + hh * 16) * P_ + p;
    uint32_t acc0 = 0, acc1 = 0;
    #pragma unroll
    for (int j = 0; j < 8; ++j) {
        float v0 = base[(size_t)(2 * j)     * P_];
        float v1 = base[(size_t)(2 * j + 1) * P_];
        acc0 |= (v0 != 0.0f ? 1u : 0u) << (2 * j);
        acc1 |= (v1 != 0.0f ? 1u : 0u) << (2 * j + 1);
    }
    g_bitsH[((l * P_ + p) << 4) + hh] = (unsigned short)(acc0 | acc1);
}

// ---------------------------------------------------------------------------
// Stage 2: bits -> packed u8 lists, padded so all 4 lists of a p-quad have the
// SAME word count (pad by duplicating the last index: idempotent under max;
// empty lists pad with 0 and are fixed by a final select in the main kernel).
// 16 CTAs x 128 threads; tiny, L2-hot.
// ---------------------------------------------------------------------------
__global__ __launch_bounds__(P_) void build_lists_kernel() {
    const int lang = blockIdx.x;
    const int p    = threadIdx.x;
    const uint32_t* gb = (const uint32_t*)g_bitsH + ((size_t)lang * P_ + p) * 8;

    unsigned char idx[4 * (SEG - 1)];      // 64 (local mem OK: cold kernel)
    int n = 0, last = 0;
    #pragma unroll
    for (int k = 0; k < 8; ++k) {
        uint32_t w = gb[k];
        while (w) {
            int bit = __ffs(w) - 1;
            w &= w - 1;
            last = k * 32 + bit;
            if (n < 64) idx[n] = (unsigned char)last;
            ++n;
        }
    }
    if (n > 64) n = 64;
    const int realc = n;
    const unsigned char fl = realc ? (unsigned char)last : (unsigned char)0;

    int m = (n + 3) >> 2;                               // own word count
    m = max(m, __shfl_xor_sync(0xffffffffu, m, 1));     // quad max (p-quads are
    m = max(m, __shfl_xor_sync(0xffffffffu, m, 2));     // warp-aligned groups of 4)
    if (m > SEG - 1) m = SEG - 1;
    while (n < 4 * m) idx[n++] = fl;

    uint32_t* dst = g_list + ((size_t)lang * P_ + p) * SEG;
    dst[0] = (uint32_t)m | ((uint32_t)realc << 16);
    for (int k = 0; k < m; ++k)
        dst[1 + k] = (uint32_t)idx[4*k] | ((uint32_t)idx[4*k+1] << 8)
                   | ((uint32_t)idx[4*k+2] << 16) | ((uint32_t)idx[4*k+3] << 24);
}

// ---------------------------------------------------------------------------
// Main: CTA = (32-t tile, b, p-half) -> 512 CTAs x 512 threads (16 warps).
// Warp = one p-quad: quarter q = p_loc wid*4+q; lane tslot tl = lane&7 holds
// t = t0 + 4*tl + c in a float4. Every gather is ONE LDS.128 serving 128
// updates, conflict-free per quarter (bank-group (s+tl)%8 distinct). The quad
// list is padded -> loop fully warp-uniform.
// ---------------------------------------------------------------------------
__global__ __launch_bounds__(512) void allophone_map_kernel(
    const float* __restrict__ logits,      // [T, B, S]
    const int*   __restrict__ lang_ids,    // [B]
    float*       __restrict__ out)         // [T, B, P]
{
    __shared__ float4   sl4[S_ * STRF];    // 36,864 B (reused as transpose buffer)
    __shared__ uint32_t slist[64 * SEG];   //  4,352 B

    const int t0    = blockIdx.x * 32;
    const int b     = blockIdx.y;
    const int p0    = blockIdx.z * 64;
    const int tid   = threadIdx.x;
    const int lane  = tid & 31;
    const int wid   = tid >> 5;
    const int q     = lane >> 3;           // quarter -> which p of the quad
    const int tl    = lane & 7;            // t-slot (4 t's per lane)
    const int p_loc = wid * 4 + q;

    const int lang = __ldg(lang_ids + b);

    // Copy this p-range's lists to smem (coalesced, 4,352 B).
    {
        const uint32_t* src = g_list + ((size_t)lang * P_ + p0) * SEG;
        #pragma unroll
        for (int i = tid; i < 64 * SEG; i += 512) slist[i] = __ldg(src + i);
    }

    // Fill tile: item = (s, t-quad). 4 coalesced LDG.32 + ONE STS.128 at
    // float4 slot s*9+tq -> bank-group (s+tq)%8 distinct per quarter: conflict-free.
    const float* lb = logits + (size_t)b * S_;
    #pragma unroll
    for (int i = 0; i < 4; ++i) {
        int g  = i * 512 + tid;
        int s  = g & (S_ - 1);
        int tq = g >> 8;                   // 0..7
        int ta = t0 + 4 * tq;
        int c0 = min(ta + 0, T_ - 1);      // tail clamp (stores guarded below)
        int c1 = min(ta + 1, T_ - 1);
        int c2 = min(ta + 2, T_ - 1);
        int c3 = min(ta + 3, T_ - 1);
        float4 v;
        v.x = lb[(size_t)c0 * (B_ * S_) + s];
        v.y = lb[(size_t)c1 * (B_ * S_) + s];
        v.z = lb[(size_t)c2 * (B_ * S_) + s];
        v.w = lb[(size_t)c3 * (B_ * S_) + s];
        sl4[s * STRF + tq] = v;
    }
    __syncthreads();

    // Gather: warp-uniform loop (quad-padded). 1 broadcast list word + 4
    // LDS.128 + 16 FMNMX per 512 warp-updates.
    const uint32_t* lw = slist + p_loc * SEG;   // banks 17q apart -> no conflict
    const uint32_t hdr = lw[0];
    const int nw    = hdr & 0xFFFFu;            // uniform across the warp
    const int realc = (int)(hdr >> 16);

    float a0 = PADV, a1 = PADV, a2 = PADV, a3 = PADV;
    for (int k = 1; k <= nw; ++k) {
        uint32_t word = lw[k];
        float4 v;
        v = sl4[(word         & 255u) * STRF + tl];
        a0 = fmaxf(a0, v.x); a1 = fmaxf(a1, v.y); a2 = fmaxf(a2, v.z); a3 = fmaxf(a3, v.w);
        v = sl4[((word >>  8) & 255u) * STRF + tl];
        a0 = fmaxf(a0, v.x); a1 = fmaxf(a1, v.y); a2 = fmaxf(a2, v.z); a3 = fmaxf(a3, v.w);
        v = sl4[((word >> 16) & 255u) * STRF + tl];
        a0 = fmaxf(a0, v.x); a1 = fmaxf(a1, v.y); a2 = fmaxf(a2, v.z); a3 = fmaxf(a3, v.w);
        v = sl4[( word >> 24        ) * STRF + tl];
        a0 = fmaxf(a0, v.x); a1 = fmaxf(a1, v.y); a2 = fmaxf(a2, v.z); a3 = fmaxf(a3, v.w);
    }
    if (realc == 0) { a0 = a1 = a2 = a3 = PADV; }   // empty-list padding was s=0
    __syncthreads();                                // all sl4 reads done before reuse

    // Transpose through reused smem: banks (4tl + c + 4wid + q) -> 32 distinct.
    float* so = (float*)sl4;                        // 32*129 floats < capacity
    so[(4 * tl + 0) * OST + p_loc] = a0;
    so[(4 * tl + 1) * OST + p_loc] = a1;
    so[(4 * tl + 2) * OST + p_loc] = a2;
    so[(4 * tl + 3) * OST + p_loc] = a3;
    __syncthreads();

    // Coalesced stores (64 contiguous p per t-row), tail-guarded.
    #pragma unroll
    for (int i = 0; i < 4; ++i) {
        int g2 = i * 512 + tid;
        int t  = g2 >> 6;
        int pc = g2 & 63;
        int tt = t0 + t;
        if (tt < T_)
            out[((size_t)tt * B_ + b) * P_ + p0 + pc] = so[t * OST + pc];
    }
}

// ---------------------------------------------------------------------------
extern "C" void kernel_launch(void* const* d_in, const int* in_sizes, int n_in,
                              void* d_out, int out_size) {
    const float* logits = (const float*)d_in[0];   // [T,B,S] f32
    const int*   langs  = (const int*)  d_in[1];   // [B] i32
    const float* mats   = (const float*)d_in[2];   // [L,S,P] f32
    // d_in[3] (mask) is redundant: mask == (mats == 0)

    build_bits_kernel <<<L_ * 16, P_>>>(mats);     // 256 CTAs
    build_lists_kernel<<<L_, P_>>>();              // 16 CTAs

    dim3 grid(16, B_, 2);                          // 512 CTAs x 512 threads
    allophone_map_kernel<<<grid, 512>>>(logits, langs, (float*)d_out);
}

// round 10
// speedup vs baseline: 1.2495x; 1.2495x over previous
#include <cuda_runtime.h>
#include <stdint.h>

// Problem constants (fixed by the dataset)
#define T_  500
#define B_  16
#define S_  256
#define P_  128
#define L_  16

#define SEG   17     // u32 per p-list: [0]=paddedWords | realCnt<<16; 16 words = 64 idx cap
#define STRF  9      // sl4 stride (float4s) per s: 8 lanes x 16B = all 32 banks per quarter
#define OST   129    // output-transpose row stride: conflict-free STS
#define PADV (-3.402823466e38f)

// Scratch (__device__ globals; allocation is forbidden). Pure fns of inputs.
__device__ unsigned short g_bitsH[L_ * P_ * 16];   // [lang][p][16] u16 membership halves
__device__ uint32_t      g_list [L_ * P_ * SEG];   // packed u8 index lists, quad-padded

// ---------------------------------------------------------------------------
// Stage 1: membership bitmask. CTA = (lang, 16-s chunk) -> 256 CTAs x 128 thr.
// Thread builds one 16-bit half-word from 16 independent coalesced loads.
// ---------------------------------------------------------------------------
__global__ __launch_bounds__(P_) void build_bits_kernel(const float* __restrict__ mats) {
    const int l  = blockIdx.x >> 4;
    const int hh = blockIdx.x & 15;
    const int p  = threadIdx.x;
    const float* base = mats + ((size_t)l * S_ + hh * 16) * P_ + p;
    uint32_t acc0 = 0, acc1 = 0;
    #pragma unroll
    for (int j = 0; j < 8; ++j) {
        float v0 = base[(size_t)(2 * j)     * P_];
        float v1 = base[(size_t)(2 * j + 1) * P_];
        acc0 |= (v0 != 0.0f ? 1u : 0u) << (2 * j);
        acc1 |= (v1 != 0.0f ? 1u : 0u) << (2 * j + 1);
    }
    g_bitsH[((l * P_ + p) << 4) + hh] = (unsigned short)(acc0 | acc1);
}

// ---------------------------------------------------------------------------
// Stage 2: warp-ballot list builder. One WARP per (lang,p): lane i owns byte i
// of the 256-bit mask; popc + shfl-scan -> per-lane write offsets; direct
// STG.8 emission (no local memory, no serial walk). Lists quad-padded (same
// word count across each aligned 4-p group) by duplicating the last index
// (idempotent under max; empty lists pad 0, fixed by select in main kernel).
// 256 CTAs x 256 threads (8 warps = 8 consecutive p).
// ---------------------------------------------------------------------------
__global__ __launch_bounds__(256) void build_lists_kernel() {
    __shared__ int stot[8];
    const int lang = blockIdx.x >> 4;
    const int p    = ((blockIdx.x & 15) << 3) + (threadIdx.x >> 5);
    const int lane = threadIdx.x & 31;
    const int w    = threadIdx.x >> 5;

    const uint32_t* gb = (const uint32_t*)g_bitsH + ((size_t)lang * P_ + p) * 8;
    uint32_t word = __ldg(gb + (lane >> 2));                 // L2-hot
    uint32_t byte = (word >> (8 * (lane & 3))) & 255u;
    int cnt = __popc(byte);

    int inc = cnt;                                           // inclusive scan
    #pragma unroll
    for (int d = 1; d < 32; d <<= 1) {
        int o = __shfl_up_sync(0xffffffffu, inc, d);
        if (lane >= d) inc += o;
    }
    const int total = __shfl_sync(0xffffffffu, inc, 31);
    const int base  = inc - cnt;

    int lastidx = cnt ? (lane * 8 + (31 - __clz(byte))) : -1;  // padding fill value
    #pragma unroll
    for (int d = 16; d; d >>= 1)
        lastidx = max(lastidx, __shfl_xor_sync(0xffffffffu, lastidx, d));
    const unsigned char fl = (unsigned char)max(lastidx, 0);

    unsigned char* dstb = (unsigned char*)(g_list + ((size_t)lang * P_ + p) * SEG + 1);
    uint32_t bb = byte; int off = base;
    while (bb) {                                             // <=8 iters, mostly <=2
        int j = __ffs(bb) - 1; bb &= bb - 1;
        if (off < 4 * (SEG - 1)) dstb[off] = (unsigned char)(lane * 8 + j);
        ++off;
    }

    const int realc = min(total, 4 * (SEG - 1));
    if (lane == 0) stot[w] = realc;
    __syncthreads();
    const int q0 = w & ~3;                                   // p-quad = warp group of 4
    int m = (max(max(stot[q0], stot[q0 + 1]), max(stot[q0 + 2], stot[q0 + 3])) + 3) >> 2;
    for (int o = realc + lane; o < 4 * m; o += 32) dstb[o] = fl;   // pad to quad width
    if (lane == 0)
        g_list[((size_t)lang * P_ + p) * SEG] = (uint32_t)m | ((uint32_t)realc << 16);
}

// ---------------------------------------------------------------------------
// Main: CTA = (32-t tile, b) -> 256 CTAs x 1024 threads (32 warps, ALL 128 p;
// tile filled ONCE per (t,b)). Warp = one p-quad: quarter q -> p = wid*4+q;
// lane slot tl = lane&7 holds t = t0+4*tl+c in a float4. Every gather is one
// LDS.128 serving 128 updates at the 4-wavefront conflict floor; quad-padded
// lists make the loop fully warp-uniform.
// ---------------------------------------------------------------------------
__global__ __launch_bounds__(1024, 2) void allophone_map_kernel(
    const float* __restrict__ logits,      // [T, B, S]
    const int*   __restrict__ lang_ids,    // [B]
    float*       __restrict__ out)         // [T, B, P]
{
    __shared__ float4   sl4[S_ * STRF];    // 36,864 B (reused as transpose buffer)
    __shared__ uint32_t slist[P_ * SEG];   //  8,704 B

    const int t0    = blockIdx.x * 32;
    const int b     = blockIdx.y;
    const int tid   = threadIdx.x;
    const int lane  = tid & 31;
    const int wid   = tid >> 5;
    const int q     = lane >> 3;           // quarter -> which p of the quad
    const int tl    = lane & 7;            // t-slot (4 t's per lane)
    const int p_loc = wid * 4 + q;

    const int lang = __ldg(lang_ids + b);

    // Copy this language's lists to smem (coalesced, 8,704 B).
    {
        const uint32_t* src = g_list + (size_t)lang * P_ * SEG;
        for (int i = tid; i < P_ * SEG; i += 1024) slist[i] = __ldg(src + i);
    }

    // Fill tile once: 2048 items (s, t-quad), 2 per thread. 4 coalesced LDG.32
    // + one STS.128 -> 8 lanes x 16B = all 32 banks per quarter: conflict-free.
    const float* lb = logits + (size_t)b * S_;
    #pragma unroll
    for (int i = 0; i < 2; ++i) {
        int g  = i * 1024 + tid;
        int s  = g & (S_ - 1);
        int tq = g >> 8;                   // 0..7
        int ta = t0 + 4 * tq;
        int c0 = min(ta + 0, T_ - 1);      // tail clamp (stores guarded below)
        int c1 = min(ta + 1, T_ - 1);
        int c2 = min(ta + 2, T_ - 1);
        int c3 = min(ta + 3, T_ - 1);
        float4 v;
        v.x = lb[(size_t)c0 * (B_ * S_) + s];
        v.y = lb[(size_t)c1 * (B_ * S_) + s];
        v.z = lb[(size_t)c2 * (B_ * S_) + s];
        v.w = lb[(size_t)c3 * (B_ * S_) + s];
        sl4[s * STRF + tq] = v;
    }
    __syncthreads();

    // Gather: warp-uniform loop. 1 broadcast list word + 4 LDS.128 + 16 FMNMX
    // per 512 warp-updates.
    const uint32_t* lw = slist + p_loc * SEG;   // banks 17q apart per quarter -> ok
    const uint32_t hdr = lw[0];
    const int nw    = hdr & 0xFFFFu;            // uniform across the warp (quad-padded)
    const int realc = (int)(hdr >> 16);

    float a0 = PADV, a1 = PADV, a2 = PADV, a3 = PADV;
    for (int k = 1; k <= nw; ++k) {
        uint32_t word = lw[k];
        float4 v;
        v = sl4[(word         & 255u) * STRF + tl];
        a0 = fmaxf(a0, v.x); a1 = fmaxf(a1, v.y); a2 = fmaxf(a2, v.z); a3 = fmaxf(a3, v.w);
        v = sl4[((word >>  8) & 255u) * STRF + tl];
        a0 = fmaxf(a0, v.x); a1 = fmaxf(a1, v.y); a2 = fmaxf(a2, v.z); a3 = fmaxf(a3, v.w);
        v = sl4[((word >> 16) & 255u) * STRF + tl];
        a0 = fmaxf(a0, v.x); a1 = fmaxf(a1, v.y); a2 = fmaxf(a2, v.z); a3 = fmaxf(a3, v.w);
        v = sl4[( word >> 24        ) * STRF + tl];
        a0 = fmaxf(a0, v.x); a1 = fmaxf(a1, v.y); a2 = fmaxf(a2, v.z); a3 = fmaxf(a3, v.w);
    }
    if (realc == 0) { a0 = a1 = a2 = a3 = PADV; }   // empty-list padding was s=0
    __syncthreads();                                // all sl4 reads done before reuse

    // Transpose through reused smem: banks (4tl + c + 4wid + q) mod 32 distinct.
    float* so = (float*)sl4;                        // 32*129 floats < capacity
    so[(4 * tl + 0) * OST + p_loc] = a0;
    so[(4 * tl + 1) * OST + p_loc] = a1;
    so[(4 * tl + 2) * OST + p_loc] = a2;
    so[(4 * tl + 3) * OST + p_loc] = a3;
    __syncthreads();

    // Coalesced stores (128 contiguous p per t-row), tail-guarded.
    #pragma unroll
    for (int i = 0; i < 4; ++i) {
        int g2 = i * 1024 + tid;
        int t  = g2 >> 7;
        int pc = g2 & (P_ - 1);
        int tt = t0 + t;
        if (tt < T_)
            out[((size_t)tt * B_ + b) * P_ + pc] = so[t * OST + pc];
    }
}

// ---------------------------------------------------------------------------
extern "C" void kernel_launch(void* const* d_in, const int* in_sizes, int n_in,
                              void* d_out, int out_size) {
    const float* logits = (const float*)d_in[0];   // [T,B,S] f32
    const int*   langs  = (const int*)  d_in[1];   // [B] i32
    const float* mats   = (const float*)d_in[2];   // [L,S,P] f32
    // d_in[3] (mask) is redundant: mask == (mats == 0)

    build_bits_kernel <<<L_ * 16, P_>>>(mats);     // 256 CTAs
    build_lists_kernel<<<L_ * 16, 256>>>();        // 256 CTAs, warp per (lang,p)

    dim3 grid(16, B_);                             // 256 CTAs x 1024 threads, 1 wave
    allophone_map_kernel<<<grid, 1024>>>(logits, langs, (float*)d_out);
}